// round 1
// baseline (speedup 1.0000x reference)
#include <cuda_runtime.h>
#include <math.h>

// ---------------- problem constants ----------------
#define BSZ   512
#define SEQ   3
#define DM    1550          // D_MODEL = 62*5*5
#define DS    16            // D_STATE
#define ED    3100          // EXPAND * D_MODEL
#define DTR   97            // DT_RANK
#define DBCN  129           // DTR + 2*DS
#define VOC   128
#define NR    (BSZ*SEQ)     // 1536 token rows
#define OE    256           // emb output dim
#define EPSF  1e-5f

// ---------------- scratch (static device memory; no runtime allocs) ----------------
__device__ float g_h    [NR*DM];        // residual stream
__device__ float g_xn   [NR*DM];        // rmsnorm output
__device__ float g_xz   [NR*2*ED];      // in_proj output (x | z)
__device__ float g_xc   [NR*ED];        // conv+silu output
__device__ float g_dbc  [NR*DBCN];      // x_proj output (dt|B|C)
__device__ float g_delta[NR*ED];        // softplus(dt @ dt_w + b)
__device__ float g_ys   [NR*ED];        // scan output * silu(z)
__device__ float g_negA [ED*DS];        // -exp(A_log[l])
__device__ float g_logit[NR*VOC];
__device__ float g_nrm  [NR*VOC];
__device__ float g_t    [NR*OE];
__device__ float g_part [384];          // 192 blocks * (sum, sumsq)
__device__ float g_stats[2];            // mean, invstd
__device__ float g_wesum[OE];           // sum_v emb_w[o,v]

__device__ __forceinline__ float siluf(float v){ return v / (1.f + expf(-v)); }

// ---------------- input layout transpose: x(b,s,f,c,e) -> h(b*s, c*25+f*5+e) ----------------
__global__ void k_transpose_in(const float* __restrict__ x){
    int i = blockIdx.x*blockDim.x + threadIdx.x;
    if (i >= NR*DM) return;
    int n = i / DM, d = i % DM;
    int c = d / 25, r = d % 25, f = r / 5, e = r % 5;
    int b = n / SEQ, s = n % SEQ;
    g_h[i] = x[(((b*SEQ + s)*5 + f)*62 + c)*5 + e];
}

// ---------------- rmsnorm: g_h -> g_xn ----------------
__global__ void k_rmsnorm(const float* __restrict__ w){
    __shared__ float sh[33];
    int n = blockIdx.x;
    const float* row = g_h + (size_t)n*DM;
    float ss = 0.f;
    for (int d = threadIdx.x; d < DM; d += blockDim.x){ float v = row[d]; ss += v*v; }
    for (int o = 16; o; o >>= 1) ss += __shfl_down_sync(0xffffffffu, ss, o);
    if ((threadIdx.x & 31) == 0) sh[threadIdx.x >> 5] = ss;
    __syncthreads();
    if (threadIdx.x < 32){
        float v = (threadIdx.x < (int)(blockDim.x >> 5)) ? sh[threadIdx.x] : 0.f;
        for (int o = 16; o; o >>= 1) v += __shfl_down_sync(0xffffffffu, v, o);
        if (threadIdx.x == 0) sh[32] = rsqrtf(v / (float)DM + EPSF);
    }
    __syncthreads();
    float sc = sh[32];
    for (int d = threadIdx.x; d < DM; d += blockDim.x)
        g_xn[(size_t)n*DM + d] = row[d] * sc * w[d];
}

// ---------------- generic TN SGEMM: C[M,N] (+)= A[M,K] * B[N,K]^T ----------------
// mode 0: C = acc ; mode 1: C += acc (residual) ; mode 2: C = softplus(acc + bias[n])
template<int BM, int BN, int BK, int TM, int TN>
__global__ void k_sgemm(const float* __restrict__ A, int lda,
                        const float* __restrict__ B, int ldb,
                        float* __restrict__ C, int ldc,
                        int M, int N, int K,
                        int mode, const float* __restrict__ bias)
{
    constexpr int THREADS = (BM/TM)*(BN/TN);
    constexpr int RPP = THREADS / BK;          // rows loaded per pass
    __shared__ float As[BK][BM+1];
    __shared__ float Bs[BK][BN+1];

    const int tid  = threadIdx.x;
    const int bm   = blockIdx.y * BM;
    const int bn   = blockIdx.x * BN;
    const int tn0  = (tid % (BN/TN)) * TN;
    const int tm0  = (tid / (BN/TN)) * TM;
    const int lk   = tid % BK;
    const int lr   = tid / BK;

    float acc[TM][TN];
    #pragma unroll
    for (int i = 0; i < TM; i++)
        #pragma unroll
        for (int j = 0; j < TN; j++) acc[i][j] = 0.f;

    for (int k0 = 0; k0 < K; k0 += BK){
        int gk = k0 + lk;
        bool kok = gk < K;
        #pragma unroll
        for (int p = 0; p < BM/RPP; p++){
            int m = lr + p*RPP;
            int gm = bm + m;
            As[lk][m] = (kok && gm < M) ? A[(size_t)gm*lda + gk] : 0.f;
        }
        #pragma unroll
        for (int p = 0; p < BN/RPP; p++){
            int nn = lr + p*RPP;
            int gn = bn + nn;
            Bs[lk][nn] = (kok && gn < N) ? B[(size_t)gn*ldb + gk] : 0.f;
        }
        __syncthreads();
        #pragma unroll
        for (int kk = 0; kk < BK; kk++){
            float a[TM], b[TN];
            #pragma unroll
            for (int i = 0; i < TM; i++) a[i] = As[kk][tm0 + i];
            #pragma unroll
            for (int j = 0; j < TN; j++) b[j] = Bs[kk][tn0 + j];
            #pragma unroll
            for (int i = 0; i < TM; i++)
                #pragma unroll
                for (int j = 0; j < TN; j++)
                    acc[i][j] = fmaf(a[i], b[j], acc[i][j]);
        }
        __syncthreads();
    }

    #pragma unroll
    for (int i = 0; i < TM; i++){
        int gm = bm + tm0 + i;
        if (gm >= M) continue;
        #pragma unroll
        for (int j = 0; j < TN; j++){
            int gn = bn + tn0 + j;
            if (gn >= N) continue;
            float v = acc[i][j];
            if (mode == 1){
                v += C[(size_t)gm*ldc + gn];
            } else if (mode == 2){
                float xv = v + bias[gn];
                v = fmaxf(xv, 0.f) + log1pf(expf(-fabsf(xv)));
            }
            C[(size_t)gm*ldc + gn] = v;
        }
    }
}

// ---------------- depthwise causal conv (S=3, D_CONV=4) + silu ----------------
__global__ void k_conv_silu(const float* __restrict__ cw, const float* __restrict__ cb){
    int e = blockIdx.x*blockDim.x + threadIdx.x;
    int b = blockIdx.y;
    if (e >= ED) return;
    size_t r0 = (size_t)(b*SEQ + 0)*(2*ED);
    size_t r1 = (size_t)(b*SEQ + 1)*(2*ED);
    size_t r2 = (size_t)(b*SEQ + 2)*(2*ED);
    float x0 = g_xz[r0 + e], x1 = g_xz[r1 + e], x2 = g_xz[r2 + e];
    float w0 = cw[e*4+0], w1 = cw[e*4+1], w2 = cw[e*4+2], w3 = cw[e*4+3];
    float bb = cb[e];
    float y0 = bb + w3*x0;
    float y1 = bb + w2*x0 + w3*x1;
    float y2 = bb + w1*x0 + w2*x1 + w3*x2;
    g_xc[(size_t)(b*SEQ + 0)*ED + e] = siluf(y0);
    g_xc[(size_t)(b*SEQ + 1)*ED + e] = siluf(y1);
    g_xc[(size_t)(b*SEQ + 2)*ED + e] = siluf(y2);
}

// ---------------- negA = -exp(A_log[l]) ----------------
__global__ void k_negA(const float* __restrict__ Alog){
    int i = blockIdx.x*blockDim.x + threadIdx.x;
    if (i < ED*DS) g_negA[i] = -expf(Alog[i]);
}

// ---------------- fused SSM scan (S=3), + D*xc, * silu(z) ----------------
__global__ void k_scan(const float* __restrict__ Dp){
    __shared__ float sB[SEQ][DS], sC[SEQ][DS];
    int e = blockIdx.x*blockDim.x + threadIdx.x;
    int b = blockIdx.y;
    int t = threadIdx.x;
    if (t < SEQ*DS){
        int s = t / DS, n = t % DS;
        size_t base = (size_t)(b*SEQ + s)*DBCN + DTR;
        sB[s][n] = g_dbc[base + n];
        sC[s][n] = g_dbc[base + DS + n];
    }
    __syncthreads();
    if (e >= ED) return;

    float nA[DS], hst[DS];
    #pragma unroll
    for (int n = 0; n < DS; n++){ nA[n] = g_negA[e*DS + n]; hst[n] = 0.f; }
    float dpe = Dp[e];

    #pragma unroll
    for (int s = 0; s < SEQ; s++){
        size_t row = (size_t)(b*SEQ + s);
        float d   = g_delta[row*ED + e];
        float xcv = g_xc[row*ED + e];
        float dx  = d * xcv;
        float y = 0.f;
        #pragma unroll
        for (int n = 0; n < DS; n++){
            float dA = __expf(d * nA[n]);
            hst[n] = dA*hst[n] + dx*sB[s][n];
            y = fmaf(hst[n], sC[s][n], y);
        }
        y += dpe * xcv;
        float z = g_xz[row*(2*ED) + ED + e];
        g_ys[row*ED + e] = y * siluf(z);
    }
}

// ---------------- logits mean/var (deterministic 2-pass) ----------------
__global__ void k_red1(){
    __shared__ float s1[32], s2[32];
    int base = blockIdx.x * 1024;
    float s = 0.f, q = 0.f;
    for (int i = threadIdx.x; i < 1024; i += 256){
        float v = g_logit[base + i];
        s += v; q += v*v;
    }
    for (int o = 16; o; o >>= 1){
        s += __shfl_down_sync(0xffffffffu, s, o);
        q += __shfl_down_sync(0xffffffffu, q, o);
    }
    if ((threadIdx.x & 31) == 0){ s1[threadIdx.x>>5] = s; s2[threadIdx.x>>5] = q; }
    __syncthreads();
    if (threadIdx.x < 32){
        float a = (threadIdx.x < 8) ? s1[threadIdx.x] : 0.f;
        float c = (threadIdx.x < 8) ? s2[threadIdx.x] : 0.f;
        for (int o = 4; o; o >>= 1){
            a += __shfl_down_sync(0xffffffffu, a, o);
            c += __shfl_down_sync(0xffffffffu, c, o);
        }
        if (threadIdx.x == 0){ g_part[blockIdx.x*2] = a; g_part[blockIdx.x*2+1] = c; }
    }
}

__global__ void k_red2(){
    __shared__ float s1[32], s2[32];
    float s = 0.f, q = 0.f;
    for (int i = threadIdx.x; i < 192; i += 256){ s += g_part[i*2]; q += g_part[i*2+1]; }
    for (int o = 16; o; o >>= 1){
        s += __shfl_down_sync(0xffffffffu, s, o);
        q += __shfl_down_sync(0xffffffffu, q, o);
    }
    if ((threadIdx.x & 31) == 0){ s1[threadIdx.x>>5] = s; s2[threadIdx.x>>5] = q; }
    __syncthreads();
    if (threadIdx.x == 0){
        float a = 0.f, c = 0.f;
        for (int i = 0; i < 8; i++){ a += s1[i]; c += s2[i]; }
        const float T = (float)(NR*VOC);
        float mean = a / T;
        float var  = c / T - mean*mean;
        g_stats[0] = mean;
        g_stats[1] = rsqrtf(var + EPSF);
    }
}

__global__ void k_nrm(){
    int i = blockIdx.x*blockDim.x + threadIdx.x;
    if (i < NR*VOC) g_nrm[i] = (g_logit[i] - g_stats[0]) * g_stats[1];
}

__global__ void k_wesum(const float* __restrict__ emb_w){
    int o = threadIdx.x;   // 256 threads
    float s = 0.f;
    for (int v = 0; v < VOC; v++) s += emb_w[o*VOC + v];
    g_wesum[o] = s;
}

// ---------------- final expand over f: out(b,f,s,o) ----------------
__global__ void k_final(const float* __restrict__ bnw, const float* __restrict__ bnb,
                        const float* __restrict__ embb, float* __restrict__ out){
    int i = blockIdx.x*blockDim.x + threadIdx.x;
    const int total = BSZ*5*SEQ*OE;
    if (i >= total) return;
    int o = i & 255;
    int s = (i >> 8) % SEQ;
    int f = (i / (OE*SEQ)) % 5;
    int b = i / (OE*SEQ*5);
    int n = b*SEQ + s;
    out[i] = bnw[f]*g_t[(size_t)n*OE + o] + bnb[f]*g_wesum[o] + embb[o];
}

// ---------------- launch ----------------
extern "C" void kernel_launch(void* const* d_in, const int* in_sizes, int n_in,
                              void* d_out, int out_size)
{
    const float* x        = (const float*)d_in[0];
    const float* in_w     = (const float*)d_in[1];
    const float* conv_w   = (const float*)d_in[2];
    const float* conv_b   = (const float*)d_in[3];
    const float* xp_w     = (const float*)d_in[4];
    const float* dt_w     = (const float*)d_in[5];
    const float* dt_b     = (const float*)d_in[6];
    const float* A_log    = (const float*)d_in[7];
    const float* D_param  = (const float*)d_in[8];
    const float* out_w    = (const float*)d_in[9];
    const float* norm_w   = (const float*)d_in[10];
    const float* normf_w  = (const float*)d_in[11];
    const float* lm_w     = (const float*)d_in[12];
    const float* bn_w     = (const float*)d_in[13];
    const float* bn_b     = (const float*)d_in[14];
    const float* emb_w    = (const float*)d_in[15];
    const float* emb_b    = (const float*)d_in[16];
    float* out = (float*)d_out;

    float *pxn, *pxz, *pxc, *pdbc, *pdelta, *pys, *ph, *plog, *pnrm, *pt;
    cudaGetSymbolAddress((void**)&ph,     g_h);
    cudaGetSymbolAddress((void**)&pxn,    g_xn);
    cudaGetSymbolAddress((void**)&pxz,    g_xz);
    cudaGetSymbolAddress((void**)&pxc,    g_xc);
    cudaGetSymbolAddress((void**)&pdbc,   g_dbc);
    cudaGetSymbolAddress((void**)&pdelta, g_delta);
    cudaGetSymbolAddress((void**)&pys,    g_ys);
    cudaGetSymbolAddress((void**)&plog,   g_logit);
    cudaGetSymbolAddress((void**)&pnrm,   g_nrm);
    cudaGetSymbolAddress((void**)&pt,     g_t);

    k_transpose_in<<<(NR*DM + 255)/256, 256>>>(x);

    for (int l = 0; l < 2; l++){
        // rmsnorm(h) -> xn
        k_rmsnorm<<<NR, 256>>>(norm_w + l*DM);
        // xz = xn @ in_w^T   (1536 x 6200, K=1550)
        k_sgemm<128,128,16,8,8><<<dim3((2*ED+127)/128, NR/128), 256>>>(
            pxn, DM, in_w + (size_t)l*2*ED*DM, DM, pxz, 2*ED, NR, 2*ED, DM, 0, nullptr);
        // conv + silu -> xc
        k_conv_silu<<<dim3((ED+255)/256, BSZ), 256>>>(conv_w + (size_t)l*ED*4, conv_b + l*ED);
        // dbc = xc @ xp_w^T  (1536 x 129, K=3100)
        k_sgemm<64,64,16,4,4><<<dim3((DBCN+63)/64, NR/64), 256>>>(
            pxc, ED, xp_w + (size_t)l*DBCN*ED, ED, pdbc, DBCN, NR, DBCN, ED, 0, nullptr);
        // delta = softplus(dt @ dt_w^T + dt_b)  (1536 x 3100, K=97)
        k_sgemm<128,128,16,8,8><<<dim3((ED+127)/128, NR/128), 256>>>(
            pdbc, DBCN, dt_w + (size_t)l*ED*DTR, DTR, pdelta, ED, NR, ED, DTR, 2, dt_b + l*ED);
        // negA
        k_negA<<<(ED*DS + 255)/256, 256>>>(A_log + (size_t)l*ED*DS);
        // scan -> ys
        k_scan<<<dim3((ED+255)/256, BSZ), 256>>>(D_param + l*ED);
        // h += ys @ out_w^T  (1536 x 1550, K=3100)
        k_sgemm<128,128,16,8,8><<<dim3((DM+127)/128, NR/128), 256>>>(
            pys, ED, out_w + (size_t)l*DM*ED, ED, ph, DM, NR, DM, ED, 1, nullptr);
    }

    // final rmsnorm -> xn
    k_rmsnorm<<<NR, 256>>>(normf_w);
    // logits = xn @ lm_w^T  (1536 x 128, K=1550)
    k_sgemm<64,64,16,4,4><<<dim3((VOC+63)/64, NR/64), 256>>>(
        pxn, DM, lm_w, DM, plog, VOC, NR, VOC, DM, 0, nullptr);
    // global mean/var of logits (per-f stats are identical: f is a broadcast axis)
    k_red1<<<192, 256>>>();
    k_red2<<<1, 256>>>();
    k_nrm<<<(NR*VOC + 255)/256, 256>>>();
    // t = nrm @ emb_w^T  (1536 x 256, K=128)
    k_sgemm<64,64,16,4,4><<<dim3((OE+63)/64, NR/64), 256>>>(
        pnrm, VOC, emb_w, VOC, pt, OE, NR, OE, VOC, 0, nullptr);
    k_wesum<<<1, 256>>>(emb_w);
    // out[b,f,s,o] = bn_w[f]*t[n,o] + bn_b[f]*wesum[o] + emb_b[o]
    k_final<<<(BSZ*5*SEQ*OE + 255)/256, 256>>>(bn_w, bn_b, emb_b, out);
}

// round 2
// speedup vs baseline: 2.0078x; 2.0078x over previous
#include <cuda_runtime.h>
#include <math.h>
#include <stdint.h>

// ---------------- problem constants ----------------
#define BSZ   512
#define SEQ   3
#define DM    1550          // D_MODEL
#define DS    16            // D_STATE
#define ED    3100          // EXPAND * D_MODEL
#define DTR   97            // DT_RANK
#define DBCN  129           // DTR + 2*DS
#define DBCP  132           // padded ldc for dbc (even, > DBCN)
#define DTWP  104           // padded ldb for dt_w (even, > DTR)
#define VOC   128
#define NR    (BSZ*SEQ)     // 1536 token rows
#define OE    256
#define EPSF  1e-5f

// ---------------- scratch (static device memory) ----------------
__device__ float g_h    [NR*DM];
__device__ float g_xn   [NR*DM];
__device__ float g_xz   [NR*2*ED];
__device__ float g_xc   [NR*ED];
__device__ float g_dbc  [NR*DBCP];
__device__ float g_delta[NR*ED];
__device__ float g_ys   [NR*ED];
__device__ float g_negA [ED*DS];
__device__ float g_dtw  [ED*DTWP];
__device__ float g_logit[NR*VOC];
__device__ float g_nrm  [NR*VOC];
__device__ float g_t    [NR*OE];
__device__ float g_part [384];
__device__ float g_stats[2];
__device__ float g_wesum[OE];

__device__ __forceinline__ float siluf(float v){ return v / (1.f + expf(-v)); }

__device__ __forceinline__ float tf32r(float x){
    uint32_t o;
    asm("cvt.rna.tf32.f32 %0, %1;" : "=r"(o) : "f"(x));
    return __uint_as_float(o);
}

__device__ __forceinline__ void mma_tf32(float c[4],
    uint32_t a0, uint32_t a1, uint32_t a2, uint32_t a3,
    uint32_t b0, uint32_t b1)
{
    asm volatile(
        "mma.sync.aligned.m16n8k8.row.col.f32.tf32.tf32.f32 "
        "{%0,%1,%2,%3}, {%4,%5,%6,%7}, {%8,%9}, {%0,%1,%2,%3};"
        : "+f"(c[0]), "+f"(c[1]), "+f"(c[2]), "+f"(c[3])
        : "r"(a0), "r"(a1), "r"(a2), "r"(a3), "r"(b0), "r"(b1));
}

// ---------------- TF32 tensor-core GEMM: C[M,N] (op)= A[M,K] * B[N,K]^T ----------------
// MT=4 -> BM=128 ; MT=2 -> BM=64.  BN=128, BK=32, 256 threads (8 warps, 2x4).
// mode 0: C = acc ; mode 1: C += acc ; mode 2: C = softplus(acc + bias[n])
// Requirements: M % BM == 0; lda, ldb even; row gk+1 readable whenever gk < K.
template<int MT>
__global__ void k_mma(const float* __restrict__ A, int lda,
                      const float* __restrict__ B, int ldb,
                      float* __restrict__ C, int ldc,
                      int M, int N, int K,
                      int mode, const float* __restrict__ bias)
{
    constexpr int BM = MT*32;
    __shared__ float As[BM][36];   // [m][k], stride 36 -> (4g+tg)%32 unique
    __shared__ float Bs[128][36];  // [n][k]

    const int tid  = threadIdx.x;
    const int wid  = tid >> 5, lane = tid & 31;
    const int g    = lane >> 2, tg = lane & 3;
    const int wm   = (wid >> 2) * (MT*16);   // 2 warp-rows
    const int wn   = (wid & 3) * 32;         // 4 warp-cols
    const int bm   = blockIdx.y * BM;
    const int bn   = blockIdx.x * 128;

    const int lk2  = tid & 15;   // float2 k-column
    const int lr   = tid >> 4;   // 0..15 row

    float acc[MT][4][4];
    #pragma unroll
    for (int mt = 0; mt < MT; mt++)
        #pragma unroll
        for (int nt = 0; nt < 4; nt++)
            #pragma unroll
            for (int i = 0; i < 4; i++) acc[mt][nt][i] = 0.f;

    for (int k0 = 0; k0 < K; k0 += 32){
        const int gk = k0 + lk2*2;
        // stage A (rows always < M)
        #pragma unroll
        for (int p = 0; p < BM/16; p++){
            int m = lr + p*16;
            float2 v = make_float2(0.f, 0.f);
            if (gk < K){
                v = *(const float2*)(A + (size_t)(bm + m)*lda + gk);
                if (gk + 1 >= K) v.y = 0.f;
            }
            As[m][lk2*2]   = tf32r(v.x);
            As[m][lk2*2+1] = tf32r(v.y);
        }
        // stage B
        #pragma unroll
        for (int p = 0; p < 8; p++){
            int n = lr + p*16;
            int gn = bn + n;
            float2 v = make_float2(0.f, 0.f);
            if (gn < N && gk < K){
                v = *(const float2*)(B + (size_t)gn*ldb + gk);
                if (gk + 1 >= K) v.y = 0.f;
            }
            Bs[n][lk2*2]   = tf32r(v.x);
            Bs[n][lk2*2+1] = tf32r(v.y);
        }
        __syncthreads();

        #pragma unroll
        for (int ks = 0; ks < 32; ks += 8){
            uint32_t af[MT][4], bf[4][2];
            #pragma unroll
            for (int mt = 0; mt < MT; mt++){
                int r = wm + mt*16 + g;
                af[mt][0] = __float_as_uint(As[r    ][ks+tg]);
                af[mt][1] = __float_as_uint(As[r + 8][ks+tg]);
                af[mt][2] = __float_as_uint(As[r    ][ks+tg+4]);
                af[mt][3] = __float_as_uint(As[r + 8][ks+tg+4]);
            }
            #pragma unroll
            for (int nt = 0; nt < 4; nt++){
                int c = wn + nt*8 + g;
                bf[nt][0] = __float_as_uint(Bs[c][ks+tg]);
                bf[nt][1] = __float_as_uint(Bs[c][ks+tg+4]);
            }
            #pragma unroll
            for (int mt = 0; mt < MT; mt++)
                #pragma unroll
                for (int nt = 0; nt < 4; nt++)
                    mma_tf32(acc[mt][nt], af[mt][0], af[mt][1], af[mt][2], af[mt][3],
                             bf[nt][0], bf[nt][1]);
        }
        __syncthreads();
    }

    // epilogue
    #pragma unroll
    for (int mt = 0; mt < MT; mt++){
        int r0 = bm + wm + mt*16 + g;
        #pragma unroll
        for (int nt = 0; nt < 4; nt++){
            int cl = bn + wn + nt*8 + 2*tg;
            #pragma unroll
            for (int i = 0; i < 4; i++){
                int rr = r0 + (i >> 1)*8;
                int cc = cl + (i & 1);
                if (cc >= N) continue;
                float v = acc[mt][nt][i];
                size_t idx = (size_t)rr*ldc + cc;
                if (mode == 1){
                    v += C[idx];
                } else if (mode == 2){
                    float xv = v + bias[cc];
                    v = fmaxf(xv, 0.f) + log1pf(expf(-fabsf(xv)));
                }
                C[idx] = v;
            }
        }
    }
}

// ---------------- input transpose: x(b,s,f,c,e) -> h(b*s, c*25+f*5+e) ----------------
__global__ void k_transpose_in(const float* __restrict__ x){
    int i = blockIdx.x*blockDim.x + threadIdx.x;
    if (i >= NR*DM) return;
    int n = i / DM, d = i % DM;
    int c = d / 25, r = d % 25, f = r / 5, e = r % 5;
    g_h[i] = x[((n*5 + f)*62 + c)*5 + e];
}

// ---------------- rmsnorm: g_h -> g_xn ----------------
__global__ void k_rmsnorm(const float* __restrict__ w){
    __shared__ float sh[33];
    int n = blockIdx.x;
    const float* row = g_h + (size_t)n*DM;
    float ss = 0.f;
    for (int d = threadIdx.x; d < DM; d += blockDim.x){ float v = row[d]; ss += v*v; }
    for (int o = 16; o; o >>= 1) ss += __shfl_down_sync(0xffffffffu, ss, o);
    if ((threadIdx.x & 31) == 0) sh[threadIdx.x >> 5] = ss;
    __syncthreads();
    if (threadIdx.x < 32){
        float v = (threadIdx.x < (int)(blockDim.x >> 5)) ? sh[threadIdx.x] : 0.f;
        for (int o = 16; o; o >>= 1) v += __shfl_down_sync(0xffffffffu, v, o);
        if (threadIdx.x == 0) sh[32] = rsqrtf(v / (float)DM + EPSF);
    }
    __syncthreads();
    float sc = sh[32];
    for (int d = threadIdx.x; d < DM; d += blockDim.x)
        g_xn[(size_t)n*DM + d] = row[d] * sc * w[d];
}

// ---------------- depthwise causal conv (S=3) + silu ----------------
__global__ void k_conv_silu(const float* __restrict__ cw, const float* __restrict__ cb){
    int e = blockIdx.x*blockDim.x + threadIdx.x;
    int b = blockIdx.y;
    if (e >= ED) return;
    size_t r0 = (size_t)(b*SEQ + 0)*(2*ED);
    size_t r1 = (size_t)(b*SEQ + 1)*(2*ED);
    size_t r2 = (size_t)(b*SEQ + 2)*(2*ED);
    float x0 = g_xz[r0 + e], x1 = g_xz[r1 + e], x2 = g_xz[r2 + e];
    float w1 = cw[e*4+1], w2 = cw[e*4+2], w3 = cw[e*4+3];
    float bb = cb[e];
    g_xc[(size_t)(b*SEQ + 0)*ED + e] = siluf(bb + w3*x0);
    g_xc[(size_t)(b*SEQ + 1)*ED + e] = siluf(bb + w2*x0 + w3*x1);
    g_xc[(size_t)(b*SEQ + 2)*ED + e] = siluf(bb + w1*x0 + w2*x1 + w3*x2);
}

// ---------------- negA = -exp(A_log[l]) ----------------
__global__ void k_negA(const float* __restrict__ Alog){
    int i = blockIdx.x*blockDim.x + threadIdx.x;
    if (i < ED*DS) g_negA[i] = -expf(Alog[i]);
}

// ---------------- pad dt_w[l] (ED x 97) -> g_dtw (ED x 104) ----------------
__global__ void k_padw(const float* __restrict__ src){
    int i = blockIdx.x*blockDim.x + threadIdx.x;
    if (i >= ED*DTR) return;
    g_dtw[(i/DTR)*DTWP + (i%DTR)] = src[i];
}

// ---------------- fused SSM scan (S=3), + D*xc, * silu(z) ----------------
__global__ void k_scan(const float* __restrict__ Dp){
    __shared__ float sB[SEQ][DS], sC[SEQ][DS];
    int e = blockIdx.x*blockDim.x + threadIdx.x;
    int b = blockIdx.y;
    int t = threadIdx.x;
    if (t < SEQ*DS){
        int s = t / DS, n = t % DS;
        size_t base = (size_t)(b*SEQ + s)*DBCP + DTR;
        sB[s][n] = g_dbc[base + n];
        sC[s][n] = g_dbc[base + DS + n];
    }
    __syncthreads();
    if (e >= ED) return;

    float nA[DS], hst[DS];
    #pragma unroll
    for (int n = 0; n < DS; n++){ nA[n] = g_negA[e*DS + n]; hst[n] = 0.f; }
    float dpe = Dp[e];

    #pragma unroll
    for (int s = 0; s < SEQ; s++){
        size_t row = (size_t)(b*SEQ + s);
        float d   = g_delta[row*ED + e];
        float xcv = g_xc[row*ED + e];
        float dx  = d * xcv;
        float y = 0.f;
        #pragma unroll
        for (int n = 0; n < DS; n++){
            float dA = __expf(d * nA[n]);
            hst[n] = dA*hst[n] + dx*sB[s][n];
            y = fmaf(hst[n], sC[s][n], y);
        }
        y += dpe * xcv;
        float z = g_xz[row*(2*ED) + ED + e];
        g_ys[row*ED + e] = y * siluf(z);
    }
}

// ---------------- logits mean/var (deterministic 2-pass) ----------------
__global__ void k_red1(){
    __shared__ float s1[32], s2[32];
    int base = blockIdx.x * 1024;
    float s = 0.f, q = 0.f;
    for (int i = threadIdx.x; i < 1024; i += 256){
        float v = g_logit[base + i];
        s += v; q += v*v;
    }
    for (int o = 16; o; o >>= 1){
        s += __shfl_down_sync(0xffffffffu, s, o);
        q += __shfl_down_sync(0xffffffffu, q, o);
    }
    if ((threadIdx.x & 31) == 0){ s1[threadIdx.x>>5] = s; s2[threadIdx.x>>5] = q; }
    __syncthreads();
    if (threadIdx.x < 32){
        float a = (threadIdx.x < 8) ? s1[threadIdx.x] : 0.f;
        float c = (threadIdx.x < 8) ? s2[threadIdx.x] : 0.f;
        for (int o = 4; o; o >>= 1){
            a += __shfl_down_sync(0xffffffffu, a, o);
            c += __shfl_down_sync(0xffffffffu, c, o);
        }
        if (threadIdx.x == 0){ g_part[blockIdx.x*2] = a; g_part[blockIdx.x*2+1] = c; }
    }
}

__global__ void k_red2(){
    __shared__ float s1[32], s2[32];
    float s = 0.f, q = 0.f;
    for (int i = threadIdx.x; i < 192; i += 256){ s += g_part[i*2]; q += g_part[i*2+1]; }
    for (int o = 16; o; o >>= 1){
        s += __shfl_down_sync(0xffffffffu, s, o);
        q += __shfl_down_sync(0xffffffffu, q, o);
    }
    if ((threadIdx.x & 31) == 0){ s1[threadIdx.x>>5] = s; s2[threadIdx.x>>5] = q; }
    __syncthreads();
    if (threadIdx.x == 0){
        float a = 0.f, c = 0.f;
        for (int i = 0; i < 8; i++){ a += s1[i]; c += s2[i]; }
        const float T = (float)(NR*VOC);
        float mean = a / T;
        float var  = c / T - mean*mean;
        g_stats[0] = mean;
        g_stats[1] = rsqrtf(var + EPSF);
    }
}

__global__ void k_nrm(){
    int i = blockIdx.x*blockDim.x + threadIdx.x;
    if (i < NR*VOC) g_nrm[i] = (g_logit[i] - g_stats[0]) * g_stats[1];
}

__global__ void k_wesum(const float* __restrict__ emb_w){
    int o = threadIdx.x;
    float s = 0.f;
    for (int v = 0; v < VOC; v++) s += emb_w[o*VOC + v];
    g_wesum[o] = s;
}

// ---------------- final expand over f: out(b,f,s,o) ----------------
__global__ void k_final(const float* __restrict__ bnw, const float* __restrict__ bnb,
                        const float* __restrict__ embb, float* __restrict__ out){
    int i = blockIdx.x*blockDim.x + threadIdx.x;
    const int total = BSZ*5*SEQ*OE;
    if (i >= total) return;
    int o = i & 255;
    int s = (i >> 8) % SEQ;
    int f = (i / (OE*SEQ)) % 5;
    int b = i / (OE*SEQ*5);
    int n = b*SEQ + s;
    out[i] = bnw[f]*g_t[(size_t)n*OE + o] + bnb[f]*g_wesum[o] + embb[o];
}

// ---------------- launch ----------------
extern "C" void kernel_launch(void* const* d_in, const int* in_sizes, int n_in,
                              void* d_out, int out_size)
{
    const float* x        = (const float*)d_in[0];
    const float* in_w     = (const float*)d_in[1];
    const float* conv_w   = (const float*)d_in[2];
    const float* conv_b   = (const float*)d_in[3];
    const float* xp_w     = (const float*)d_in[4];
    const float* dt_w     = (const float*)d_in[5];
    const float* dt_b     = (const float*)d_in[6];
    const float* A_log    = (const float*)d_in[7];
    const float* D_param  = (const float*)d_in[8];
    const float* out_w    = (const float*)d_in[9];
    const float* norm_w   = (const float*)d_in[10];
    const float* normf_w  = (const float*)d_in[11];
    const float* lm_w     = (const float*)d_in[12];
    const float* bn_w     = (const float*)d_in[13];
    const float* bn_b     = (const float*)d_in[14];
    const float* emb_w    = (const float*)d_in[15];
    const float* emb_b    = (const float*)d_in[16];
    float* out = (float*)d_out;

    float *pxn, *pxz, *pxc, *pdbc, *pdelta, *pys, *ph, *plog, *pnrm, *pt, *pdtw;
    cudaGetSymbolAddress((void**)&ph,     g_h);
    cudaGetSymbolAddress((void**)&pxn,    g_xn);
    cudaGetSymbolAddress((void**)&pxz,    g_xz);
    cudaGetSymbolAddress((void**)&pxc,    g_xc);
    cudaGetSymbolAddress((void**)&pdbc,   g_dbc);
    cudaGetSymbolAddress((void**)&pdelta, g_delta);
    cudaGetSymbolAddress((void**)&pys,    g_ys);
    cudaGetSymbolAddress((void**)&plog,   g_logit);
    cudaGetSymbolAddress((void**)&pnrm,   g_nrm);
    cudaGetSymbolAddress((void**)&pt,     g_t);
    cudaGetSymbolAddress((void**)&pdtw,   g_dtw);

    k_transpose_in<<<(NR*DM + 255)/256, 256>>>(x);

    for (int l = 0; l < 2; l++){
        // rmsnorm(h) -> xn
        k_rmsnorm<<<NR, 256>>>(norm_w + l*DM);
        // xz = xn @ in_w^T   (1536 x 6200, K=1550)
        k_mma<4><<<dim3(49, 12), 256>>>(
            pxn, DM, in_w + (size_t)l*2*ED*DM, DM, pxz, 2*ED, NR, 2*ED, DM, 0, nullptr);
        // conv + silu -> xc
        k_conv_silu<<<dim3((ED+255)/256, BSZ), 256>>>(conv_w + (size_t)l*ED*4, conv_b + l*ED);
        // dbc = xc @ xp_w^T  (1536 x 129, K=3100) -> ldc padded to 132
        k_mma<2><<<dim3(2, 24), 256>>>(
            pxc, ED, xp_w + (size_t)l*DBCN*ED, ED, pdbc, DBCP, NR, DBCN, ED, 0, nullptr);
        // pad dt_w for even-stride loads
        k_padw<<<(ED*DTR + 255)/256, 256>>>(dt_w + (size_t)l*ED*DTR);
        // delta = softplus(dt @ dt_w^T + dt_b)  (1536 x 3100, K=97)
        k_mma<4><<<dim3(25, 12), 256>>>(
            pdbc, DBCP, pdtw, DTWP, pdelta, ED, NR, ED, DTR, 2, dt_b + l*ED);
        // negA
        k_negA<<<(ED*DS + 255)/256, 256>>>(A_log + (size_t)l*ED*DS);
        // scan -> ys
        k_scan<<<dim3((ED+255)/256, BSZ), 256>>>(D_param + l*ED);
        // h += ys @ out_w^T  (1536 x 1550, K=3100)
        k_mma<4><<<dim3(13, 12), 256>>>(
            pys, ED, out_w + (size_t)l*DM*ED, ED, ph, DM, NR, DM, ED, 1, nullptr);
    }

    // final rmsnorm -> xn
    k_rmsnorm<<<NR, 256>>>(normf_w);
    // logits = xn @ lm_w^T  (1536 x 128, K=1550)
    k_mma<2><<<dim3(1, 24), 256>>>(
        pxn, DM, lm_w, DM, plog, VOC, NR, VOC, DM, 0, nullptr);
    // global mean/var of logits (per-f stats identical: f is a broadcast axis)
    k_red1<<<192, 256>>>();
    k_red2<<<1, 256>>>();
    k_nrm<<<(NR*VOC + 255)/256, 256>>>();
    // t = nrm @ emb_w^T  (1536 x 256, K=128)
    k_mma<2><<<dim3(2, 24), 256>>>(
        pnrm, VOC, emb_w, VOC, pt, OE, NR, OE, VOC, 0, nullptr);
    k_wesum<<<1, 256>>>(emb_w);
    // out[b,f,s,o] = bn_w[f]*t[n,o] + bn_b[f]*wesum[o] + emb_b[o]
    k_final<<<(BSZ*5*SEQ*OE + 255)/256, 256>>>(bn_w, bn_b, emb_b, out);
}